// round 1
// baseline (speedup 1.0000x reference)
#include <cuda_runtime.h>
#include <math.h>

#define DD 160

// Scratch for conv output y [B=2, 160,160,160]
static __device__ float g_y[2 * DD * DD * DD];

static __device__ __forceinline__ int clampi(int v) {
    return min(DD - 1, max(0, v));
}

// ---------------------------------------------------------------------------
// Pass 1: 3D conv 5x5x5, replicate padding, C_in = C_out = 1.
// Tile: 32x (4 groups * 8 per thread) x 16y x 4z(per thread). 64 threads.
// Smem x tile: 8 z-slices x 20 y-rows x 36 x (stride 37 -> conflict-free).
// ---------------------------------------------------------------------------
__global__ __launch_bounds__(64) void conv3d_kernel(
    const float* __restrict__ x, const float* __restrict__ w)
{
    __shared__ float s[8 * 20 * 37];
    __shared__ float ws[125];

    const int tx = threadIdx.x;              // 0..3  (x group)
    const int ty = threadIdx.y;              // 0..15 (y)
    const int tid = ty * 4 + tx;

    const int bx0 = blockIdx.x * 32;
    const int by0 = blockIdx.y * 16;
    const int b   = blockIdx.z / 40;
    const int bz0 = (blockIdx.z % 40) * 4;

    const float* xb = x + (size_t)b * DD * DD * DD;

    for (int i = tid; i < 125; i += 64) ws[i] = w[i];

    // Load 8 x 20 x 36 halo tile, replicate-clamped
    for (int idx = tid; idx < 8 * 20 * 36; idx += 64) {
        int sz = idx / (20 * 36);
        int r  = idx % (20 * 36);
        int sy = r / 36;
        int sx = r % 36;
        int gz = clampi(bz0 + sz - 2);
        int gy = clampi(by0 + sy - 2);
        int gx = clampi(bx0 + sx - 2);
        s[sz * 740 + sy * 37 + sx] = xb[((size_t)gz * DD + gy) * DD + gx];
    }
    __syncthreads();

    float acc[4][8];
#pragma unroll
    for (int a = 0; a < 4; a++)
#pragma unroll
        for (int o = 0; o < 8; o++) acc[a][o] = 0.f;

    const int xoff = tx * 8;

    for (int sz = 0; sz < 8; sz++) {
#pragma unroll
        for (int dy = 0; dy < 5; dy++) {
            float r[12];
            const float* row = &s[sz * 740 + (ty + dy) * 37 + xoff];
#pragma unroll
            for (int i = 0; i < 12; i++) r[i] = row[i];
#pragma unroll
            for (int tz = 0; tz < 4; tz++) {
                int dz = sz - tz;
                if (dz < 0 || dz > 4) continue;
                const float* wr = &ws[(dz * 5 + dy) * 5];
                float w0 = wr[0], w1 = wr[1], w2 = wr[2], w3 = wr[3], w4 = wr[4];
#pragma unroll
                for (int o = 0; o < 8; o++) {
                    float a = acc[tz][o];
                    a = fmaf(w0, r[o + 0], a);
                    a = fmaf(w1, r[o + 1], a);
                    a = fmaf(w2, r[o + 2], a);
                    a = fmaf(w3, r[o + 3], a);
                    a = fmaf(w4, r[o + 4], a);
                    acc[tz][o] = a;
                }
            }
        }
    }

    float* yb = g_y + (size_t)b * DD * DD * DD;
#pragma unroll
    for (int tz = 0; tz < 4; tz++) {
        float* orow = yb + ((size_t)(bz0 + tz) * DD + (by0 + ty)) * DD + bx0 + xoff;
#pragma unroll
        for (int o = 0; o < 8; o++) orow[o] = acc[tz][o];
    }
}

// ---------------------------------------------------------------------------
// Exact jnp.gradient(gradient) composition for boundary voxels.
// grad: i==0 -> f[1]-f[0]; i==N-1 -> f[N-1]-f[N-2]; else (f[i+1]-f[i-1])/2.
// ---------------------------------------------------------------------------
template <typename F>
__device__ __forceinline__ float hdiag(F f, int i) {
    auto g = [&](int j) -> float {
        if (j == 0)      return f(1 - i) - f(0 - i);
        if (j == DD - 1) return f(DD - 1 - i) - f(DD - 2 - i);
        return 0.5f * (f(j + 1 - i) - f(j - 1 - i));
    };
    if (i == 0)      return g(1) - g(0);
    if (i == DD - 1) return g(DD - 1) - g(DD - 2);
    return 0.5f * (g(i + 1) - g(i - 1));
}

// h = grad_{a1}( grad_{a0}( y ) ): f(d0,d1) offsets on (a0,a1); i0 on a0, i1 on a1.
template <typename F2>
__device__ __forceinline__ float hmix(F2 f, int i0, int i1) {
    auto g = [&](int j1) -> float {
        auto f1 = [&](int k0) { return f(k0 - i0, j1 - i1); };
        if (i0 == 0)      return f1(1) - f1(0);
        if (i0 == DD - 1) return f1(DD - 1) - f1(DD - 2);
        return 0.5f * (f1(i0 + 1) - f1(i0 - 1));
    };
    if (i1 == 0)      return g(1) - g(0);
    if (i1 == DD - 1) return g(DD - 1) - g(DD - 2);
    return 0.5f * (g(i1 + 1) - g(i1 - 1));
}

// ---------------------------------------------------------------------------
// Pass 2: Hessian (6 comps) + MLP(6->10 relu ->1 sigmoid) per voxel.
// Tile: 32x x 8y x 4z(per-thread loop). 256 threads.
// Smem y tile: 8 z x 12 y x 36 x (stride 37).
// ---------------------------------------------------------------------------
__global__ __launch_bounds__(256) void hess_mlp_kernel(
    const float* __restrict__ w1, const float* __restrict__ b1,
    const float* __restrict__ w2, const float* __restrict__ b2,
    float* __restrict__ out)
{
    __shared__ float s[8 * 12 * 37];
    __shared__ float sw1[60], sb1[10], sw2[10], sb2s[1];

    const int tx = threadIdx.x;   // 0..31
    const int ty = threadIdx.y;   // 0..7
    const int tid = ty * 32 + tx;

    const int bx0 = blockIdx.x * 32;
    const int by0 = blockIdx.y * 8;
    const int b   = blockIdx.z / 40;
    const int bz0 = (blockIdx.z % 40) * 4;

    const float* yb = g_y + (size_t)b * DD * DD * DD;

    if (tid < 60)        sw1[tid] = w1[tid];
    else if (tid < 70)   sb1[tid - 60] = b1[tid - 60];
    else if (tid < 80)   sw2[tid - 70] = w2[tid - 70];
    else if (tid == 80)  sb2s[0] = b2[0];

    for (int idx = tid; idx < 8 * 12 * 36; idx += 256) {
        int sz = idx / (12 * 36);
        int r  = idx % (12 * 36);
        int sy = r / 36;
        int sx = r % 36;
        int gz = clampi(bz0 + sz - 2);
        int gy = clampi(by0 + sy - 2);
        int gx = clampi(bx0 + sx - 2);
        s[sz * 444 + sy * 37 + sx] = yb[((size_t)gz * DD + gy) * DD + gx];
    }
    __syncthreads();

    const int gx = bx0 + tx;
    const int gy = by0 + ty;

    float h[4][6];
#pragma unroll
    for (int tz = 0; tz < 4; tz++) {
        const int gz = bz0 + tz;
        const float* c = &s[(tz + 2) * 444 + (ty + 2) * 37 + (tx + 2)];
        auto O = [&](int dz, int dy, int dx) { return c[dz * 444 + dy * 37 + dx]; };

        bool interior = (gz >= 2 && gz <= DD - 3 && gy >= 2 && gy <= DD - 3 &&
                         gx >= 2 && gx <= DD - 3);
        if (interior) {
            float cc = O(0, 0, 0);
            h[tz][0] = 0.25f * (O(2, 0, 0) - 2.f * cc + O(-2, 0, 0));              // d2/dz2
            h[tz][1] = 0.25f * (O(1, 1, 0) - O(1, -1, 0) - O(-1, 1, 0) + O(-1, -1, 0)); // dz dy
            h[tz][2] = 0.25f * (O(1, 0, 1) - O(1, 0, -1) - O(-1, 0, 1) + O(-1, 0, -1)); // dz dx
            h[tz][3] = 0.25f * (O(0, 2, 0) - 2.f * cc + O(0, -2, 0));              // d2/dy2
            h[tz][4] = 0.25f * (O(0, 1, 1) - O(0, 1, -1) - O(0, -1, 1) + O(0, -1, -1)); // dy dx
            h[tz][5] = 0.25f * (O(0, 0, 2) - 2.f * cc + O(0, 0, -2));              // d2/dx2
        } else {
            h[tz][0] = hdiag([&](int d) { return O(d, 0, 0); }, gz);
            h[tz][1] = hmix([&](int d0, int d1) { return O(d0, d1, 0); }, gz, gy);
            h[tz][2] = hmix([&](int d0, int d1) { return O(d0, 0, d1); }, gz, gx);
            h[tz][3] = hdiag([&](int d) { return O(0, d, 0); }, gy);
            h[tz][4] = hmix([&](int d0, int d1) { return O(0, d0, d1); }, gy, gx);
            h[tz][5] = hdiag([&](int d) { return O(0, 0, d); }, gx);
        }
    }

    // MLP: z1 = relu(W1 h + b1); out = sigmoid(W2 z1 + b2)
    float a2[4];
#pragma unroll
    for (int v = 0; v < 4; v++) a2[v] = sb2s[0];

#pragma unroll
    for (int o = 0; o < 10; o++) {
        float wr[6];
#pragma unroll
        for (int f = 0; f < 6; f++) wr[f] = sw1[o * 6 + f];
        const float bo  = sb1[o];
        const float w2o = sw2[o];
#pragma unroll
        for (int v = 0; v < 4; v++) {
            float t = bo;
#pragma unroll
            for (int f = 0; f < 6; f++) t = fmaf(wr[f], h[v][f], t);
            t = fmaxf(t, 0.f);
            a2[v] = fmaf(w2o, t, a2[v]);
        }
    }

#pragma unroll
    for (int tz = 0; tz < 4; tz++) {
        float sg = 1.f / (1.f + __expf(-a2[tz]));
        out[(((size_t)b * DD + (bz0 + tz)) * DD + gy) * DD + gx] = sg;
    }
}

// ---------------------------------------------------------------------------
// Launch: inputs per metadata order: x, conv_w, w1, b1, w2, b2
// ---------------------------------------------------------------------------
extern "C" void kernel_launch(void* const* d_in, const int* in_sizes, int n_in,
                              void* d_out, int out_size)
{
    const float* x  = (const float*)d_in[0];
    const float* cw = (const float*)d_in[1];
    const float* w1 = (const float*)d_in[2];
    const float* b1 = (const float*)d_in[3];
    const float* w2 = (const float*)d_in[4];
    const float* b2 = (const float*)d_in[5];
    float* out = (float*)d_out;

    // Pass 1: conv. Grid: x:160/32=5, y:160/16=10, z:(160/4)*B=80
    conv3d_kernel<<<dim3(5, 10, 80), dim3(4, 16, 1)>>>(x, cw);
    // Pass 2: hessian + MLP. Grid: x:5, y:160/8=20, z:80
    hess_mlp_kernel<<<dim3(5, 20, 80), dim3(32, 8, 1)>>>(w1, b1, w2, b2, out);
}